// round 3
// baseline (speedup 1.0000x reference)
#include <cuda_runtime.h>
#include <cstddef>

// Problem shape
#define BATCH 4096
#define FN    1024
#define RC    19
#define RD    1024
#define FLAT  (FN * RC)          // 19456 floats per conv batch row
#define HALF_FLOATS (FLAT / 2)   // 9728 (== 19*512, so residues mod 19 unchanged)
#define HALF_F4     (HALF_FLOATS / 4)  // 2432

#define NBLKS  592               // exactly 4 blocks x 148 SMs -> all resident, wave 1
#define NWARPS (NBLKS * 8)       // 4736
#define NTASK  (BATCH * 2)       // 8192 half-batch tasks

// W[f][r] = sum_e U[f,e]*R[r,e], flat layout matching conv's [f*19+r]
__device__ float    g_W[FLAT];
__device__ unsigned g_sync[2];   // [0] = score task counter, [1] = W arrivals (zeroed per launch)

__device__ __forceinline__ unsigned acq_load(const unsigned* p) {
    unsigned v;
    asm volatile("ld.acquire.gpu.global.u32 %0, [%1];" : "=r"(v) : "l"(p));
    return v;
}

__global__ __launch_bounds__(256, 4)
void fused_kernel(const float* __restrict__ conv,
                  const float* __restrict__ U,
                  const float* __restrict__ R,
                  float* __restrict__ out) {
    const int lane = threadIdx.x & 31;
    const int w    = blockIdx.x * 8 + (threadIdx.x >> 5);   // 0..4735

    // ================= Phase 1: W = U @ R^T =================
    // 5 contiguous (f,r) pairs per warp -> U-row reuse in L1 within warp/block.
    {
        int p_end = w * 5 + 5;
        if (p_end > FLAT) p_end = FLAT;
        for (int p = w * 5; p < p_end; p++) {
            const int f = p / RC;
            const int r = p - f * RC;
            const float4* u4 = reinterpret_cast<const float4*>(U + (size_t)f * RD);
            const float4* r4 = reinterpret_cast<const float4*>(R + (size_t)r * RD);
            float s = 0.f;
#pragma unroll
            for (int i = 0; i < 8; i++) {
                float4 a = u4[lane + 32 * i];
                float4 b = r4[lane + 32 * i];
                s += a.x * b.x + a.y * b.y + a.z * b.z + a.w * b.w;
            }
#pragma unroll
            for (int off = 16; off > 0; off >>= 1)
                s += __shfl_xor_sync(0xffffffffu, s, off);
            if (lane == 0) g_W[p] = s;
        }
    }

    // Release: make W globally visible, then arrive.
    __threadfence();
    if (lane == 0) atomicAdd(&g_sync[1], 1u);

    // Acquire spin: all warps wait until every warp has arrived.
    unsigned v;
    while ((v = acq_load(&g_sync[1])) < (unsigned)NWARPS) __nanosleep(128);
    asm volatile("" ::: "memory");
    // Data-dependency trick: (v - NWARPS) == 0, forces W/conv reads after spin.
    const float* convd = conv + (v - (unsigned)NWARPS);

    // ================= Phase 2: streaming scores =================
    // Half-batch tasks; first task static (== warp id), rest via atomic counter.
    const float4* wbase = reinterpret_cast<const float4*>(g_W);

    unsigned t = (unsigned)w;
    for (;;) {
        if (t >= (unsigned)NTASK) break;
        const int b    = (int)(t >> 1);
        const int half = (int)(t & 1);

        const float4* c4 = reinterpret_cast<const float4*>(convd + (size_t)b * FLAT)
                           + half * HALF_F4;
        const float4* w4 = wbase + half * HALF_F4;

        float acc[RC];
#pragma unroll
        for (int k = 0; k < RC; k++) acc[k] = 0.f;

        // 76 warp-iterations = 4 outer x 19 inner (slot pattern period 19).
        // flat-in-half idx = i*128 + 4*lane + j, i = o*19 + t2:
        //   r = (14*t2 + 4*lane + j) mod 19, slot k = (14*t2 + j) mod 19.
        for (int o = 0; o < 4; o++) {
            const int base = o * (19 * 32) + lane;
#pragma unroll
            for (int t2 = 0; t2 < 19; t2++) {
                float4 cv = __ldcs(&c4[base + t2 * 32]);   // streaming, read-once
                float4 wv = __ldg(&w4[base + t2 * 32]);    // L1-resident broadcast
                acc[(14 * t2 + 0) % RC] += cv.x * wv.x;
                acc[(14 * t2 + 1) % RC] += cv.y * wv.y;
                acc[(14 * t2 + 2) % RC] += cv.z * wv.z;
                acc[(14 * t2 + 3) % RC] += cv.w * wv.w;
            }
        }

        // Warp butterfly with static residue rotation:
        // lane l slot k holds r=(4l+k)%19; peer at l+d holds it in slot (k-4d)%19.
#pragma unroll
        for (int d = 16; d >= 1; d >>= 1) {
            float tmp[RC];
#pragma unroll
            for (int k = 0; k < RC; k++) {
                const int s = (k + 4 * RC - 4 * d) % RC;
                tmp[k] = __shfl_down_sync(0xffffffffu, acc[s], d);
            }
#pragma unroll
            for (int k = 0; k < RC; k++) acc[k] += tmp[k];
        }

        // Lane 0 slot k == relation k. Merge halves into zeroed out.
        // Deterministic: exactly two commutative adds onto 0.0f.
        if (lane == 0) {
            float* ob = out + (size_t)b * RC;
#pragma unroll
            for (int k = 0; k < RC; k++) atomicAdd(&ob[k], acc[k]);
        }

        unsigned nt = 0;
        if (lane == 0) nt = (unsigned)NWARPS + atomicAdd(&g_sync[0], 1u);
        t = __shfl_sync(0xffffffffu, nt, 0);
    }
}

// ---------------------------------------------------------------------------
// Launch
// ---------------------------------------------------------------------------
extern "C" void kernel_launch(void* const* d_in, const int* in_sizes, int n_in,
                              void* d_out, int out_size) {
    const float* conv = nullptr;
    const float* R    = nullptr;
    const float* U    = nullptr;
    for (int i = 0; i < n_in; i++) {
        long long n = in_sizes[i];
        if (n == (long long)BATCH * FN * RC)      conv = (const float*)d_in[i];
        else if (n == (long long)RC * RD)         R    = (const float*)d_in[i];
        else if (n == (long long)FN * RD)         U    = (const float*)d_in[i];
    }
    float* out = (float*)d_out;

    // Zero sync counters and output accumulator (graph-capturable, no allocs).
    void* sym = nullptr;
    cudaGetSymbolAddress(&sym, g_sync);
    cudaMemsetAsync(sym, 0, 2 * sizeof(unsigned));
    cudaMemsetAsync(out, 0, (size_t)out_size * sizeof(float));

    fused_kernel<<<NBLKS, 256>>>(conv, U, R, out);
}

// round 4
// speedup vs baseline: 1.1885x; 1.1885x over previous
#include <cuda_runtime.h>
#include <cstddef>

// Problem shape
#define BATCH 4096
#define FN    1024
#define RC    19
#define RD    1024
#define FLAT  (FN * RC)            // 19456 floats per conv batch row

// Score-phase decomposition: eighth-batch tasks.
// chunk = 2432 floats (= 19*128) -> residue pattern identical in every chunk.
#define CH_FLOATS 2432
#define CH_F4     (CH_FLOATS / 4)  // 608
#define NTASK     (BATCH * 8)      // 32768
#define NBLKS     592              // 4 blocks x 148 SMs, all resident in wave 1
#define NWARPS    (NBLKS * 8)      // 4736

#define W_SMEM_BYTES (FLAT * 4)    // 77824 B: all of W-source R? no: all of... (R is 19456 floats = 77824 B)

__device__ float    g_W[FLAT];     // W[f][r] flat, matches conv's [f*19+r]
__device__ unsigned g_task;        // score task counter (zeroed per launch)

// ---------------------------------------------------------------------------
// Kernel 1: W = U @ R^T with R staged in shared memory.
// 128 blocks x 256 threads. Each block: load R (76 KB) to smem once, then
// warp i computes f = blk*8 + i: U row in regs (8 float4/lane), 19 smem dots.
// Global traffic: U 4 MB (once) + R 128x76KB = 9.7 MB L2  (was 155 MB).
// ---------------------------------------------------------------------------
__global__ void compute_w_kernel(const float* __restrict__ U,
                                 const float* __restrict__ R) {
    extern __shared__ float sR[];                 // FLAT floats
    const int tid  = threadIdx.x;
    const int lane = tid & 31;
    const int wid  = tid >> 5;

    // Stage R: 4864 float4 / 256 threads = 19 each, coalesced.
    {
        float4* s4 = reinterpret_cast<float4*>(sR);
        const float4* g4 = reinterpret_cast<const float4*>(R);
#pragma unroll
        for (int k = 0; k < 19; k++)
            s4[tid + 256 * k] = g4[tid + 256 * k];
    }
    __syncthreads();

    const int f = blockIdx.x * 8 + wid;
    const float4* u4 = reinterpret_cast<const float4*>(U + (size_t)f * RD);
    float4 u[8];
#pragma unroll
    for (int i = 0; i < 8; i++) u[i] = u4[lane + 32 * i];

    for (int r = 0; r < RC; r++) {
        const float4* r4 = reinterpret_cast<const float4*>(sR + (size_t)r * RD);
        float s = 0.f;
#pragma unroll
        for (int i = 0; i < 8; i++) {
            float4 rv = r4[lane + 32 * i];
            s += u[i].x * rv.x + u[i].y * rv.y + u[i].z * rv.z + u[i].w * rv.w;
        }
#pragma unroll
        for (int off = 16; off > 0; off >>= 1)
            s += __shfl_xor_sync(0xffffffffu, s, off);
        if (lane == 0) g_W[f * RC + r] = s;
    }
}

// ---------------------------------------------------------------------------
// Kernel 2: score[b][r] = sum_f conv[b][f][r] * W[f][r]
//
// Persistent warps, dynamic eighth-batch tasks (32768 tasks / 4736 warps =
// 6.92 -> 98.8% quantization efficiency; first task static to avoid an
// atomic burst at t=0). Each task: 19 unit-stride float4 LDGs of conv
// (perfect coalescing, __ldcs evict-first) paired with L1-resident W reads.
//
// Rotating register accumulators, compile-time slots:
//   chunk-local idx = i*128 + 4*lane + j  (chunk base = 0 mod 19)
//   r = (14*i + 4*lane + j) mod 19, slot k = (14*i + j) mod 19.
// Warp butterfly with static residue rotation; lane 0 slot k == r.
// Partials merged with atomicAdd into memset-zeroed out (8 adds/element).
// ---------------------------------------------------------------------------
__global__ __launch_bounds__(256, 4)
void score_kernel(const float* __restrict__ conv, float* __restrict__ out) {
    const int lane = threadIdx.x & 31;
    const int w    = blockIdx.x * 8 + (threadIdx.x >> 5);   // 0..4735

    const float4* wbase = reinterpret_cast<const float4*>(g_W);

    unsigned t = (unsigned)w;   // static first task; counter pre-offset by NWARPS
    while (t < (unsigned)NTASK) {
        const int b  = (int)(t >> 3);
        const int ch = (int)(t & 7);

        const float4* c4 = reinterpret_cast<const float4*>(conv + (size_t)b * FLAT)
                           + ch * CH_F4;
        const float4* w4 = wbase + ch * CH_F4;

        float acc[RC];
#pragma unroll
        for (int k = 0; k < RC; k++) acc[k] = 0.f;

#pragma unroll
        for (int i = 0; i < 19; i++) {
            float4 cv = __ldcs(&c4[i * 32 + lane]);   // DRAM stream, read-once
            float4 wv = __ldg(&w4[i * 32 + lane]);    // L1-resident
            acc[(14 * i + 0) % RC] += cv.x * wv.x;
            acc[(14 * i + 1) % RC] += cv.y * wv.y;
            acc[(14 * i + 2) % RC] += cv.z * wv.z;
            acc[(14 * i + 3) % RC] += cv.w * wv.w;
        }

        // Butterfly: lane l slot k holds r=(4l+k)%19; peer l+d has it at (k-4d)%19.
#pragma unroll
        for (int d = 16; d >= 1; d >>= 1) {
            float tmp[RC];
#pragma unroll
            for (int k = 0; k < RC; k++) {
                const int s = (k + 4 * RC - 4 * d) % RC;
                tmp[k] = __shfl_down_sync(0xffffffffu, acc[s], d);
            }
#pragma unroll
            for (int k = 0; k < RC; k++) acc[k] += tmp[k];
        }

        if (lane == 0) {
            float* ob = out + (size_t)b * RC;
#pragma unroll
            for (int k = 0; k < RC; k++) atomicAdd(&ob[k], acc[k]);
        }

        unsigned nt = 0;
        if (lane == 0) nt = (unsigned)NWARPS + atomicAdd(&g_task, 1u);
        t = __shfl_sync(0xffffffffu, nt, 0);
    }
}

// ---------------------------------------------------------------------------
// Launch
// ---------------------------------------------------------------------------
extern "C" void kernel_launch(void* const* d_in, const int* in_sizes, int n_in,
                              void* d_out, int out_size) {
    const float* conv = nullptr;
    const float* R    = nullptr;
    const float* U    = nullptr;
    for (int i = 0; i < n_in; i++) {
        long long n = in_sizes[i];
        if (n == (long long)BATCH * FN * RC)      conv = (const float*)d_in[i];
        else if (n == (long long)RC * RD)         R    = (const float*)d_in[i];
        else if (n == (long long)FN * RD)         U    = (const float*)d_in[i];
    }
    float* out = (float*)d_out;

    // Zero task counter and output accumulator (async, graph-capturable).
    void* sym = nullptr;
    cudaGetSymbolAddress(&sym, g_task);
    cudaMemsetAsync(sym, 0, sizeof(unsigned));
    cudaMemsetAsync(out, 0, (size_t)out_size * sizeof(float));

    cudaFuncSetAttribute(compute_w_kernel,
                         cudaFuncAttributeMaxDynamicSharedMemorySize, W_SMEM_BYTES);
    compute_w_kernel<<<128, 256, W_SMEM_BYTES>>>(U, R);
    score_kernel<<<NBLKS, 256>>>(conv, out);
}

// round 5
// speedup vs baseline: 1.2949x; 1.0894x over previous
#include <cuda_runtime.h>
#include <cstddef>

// Problem shape
#define BATCH 4096
#define FN    1024
#define RC    19
#define RD    1024
#define FLAT  (FN * RC)            // 19456 floats per conv batch row

#define W_SMEM_BYTES (FLAT * 4)    // 77824 B (all of R staged in smem)

__device__ float g_W[FLAT];        // W[f][r] flat, matches conv's [f*19+r]

// ---------------------------------------------------------------------------
// Kernel 1: W = U @ R^T with R staged in shared memory.
// 128 blocks x 256 threads; block stages R (76 KB) once, warp i computes
// f = blk*8 + i with its U row in registers. L2 traffic ~14 MB total.
// ---------------------------------------------------------------------------
__global__ void compute_w_kernel(const float* __restrict__ U,
                                 const float* __restrict__ R) {
    extern __shared__ float sR[];
    const int tid  = threadIdx.x;
    const int lane = tid & 31;
    const int wid  = tid >> 5;

    {
        float4* s4 = reinterpret_cast<float4*>(sR);
        const float4* g4 = reinterpret_cast<const float4*>(R);
#pragma unroll
        for (int k = 0; k < 19; k++)
            s4[tid + 256 * k] = g4[tid + 256 * k];
    }
    __syncthreads();

    const int f = blockIdx.x * 8 + wid;
    const float4* u4 = reinterpret_cast<const float4*>(U + (size_t)f * RD);
    float4 u[8];
#pragma unroll
    for (int i = 0; i < 8; i++) u[i] = u4[lane + 32 * i];

    for (int r = 0; r < RC; r++) {
        const float4* r4 = reinterpret_cast<const float4*>(sR + (size_t)r * RD);
        float s = 0.f;
#pragma unroll
        for (int i = 0; i < 8; i++) {
            float4 rv = r4[lane + 32 * i];
            s += u[i].x * rv.x + u[i].y * rv.y + u[i].z * rv.z + u[i].w * rv.w;
        }
#pragma unroll
        for (int off = 16; off > 0; off >>= 1)
            s += __shfl_xor_sync(0xffffffffu, s, off);
        if (lane == 0) g_W[f * RC + r] = s;
    }
}

// ---------------------------------------------------------------------------
// Kernel 2: score[b][r] = sum_f conv[b][f][r] * W[f][r]
//
// Grid = 4 blocks per SM (all resident, single wave). Static Bresenham
// assignment: block bid owns a contiguous run of 6 or 7 whole batches
// (k6 = 7*NB - 4096 blocks carry 6, spread uniformly in bid space so every
// SM hosts 27-28 busy warps). Warp wid handles batch base+wid. Zero atomics,
// zero memsets; every batch statically owned exactly once.
//
// Hot path per warp (identical to the proven r2 structure):
//   152 unit-stride float4 LDGs (__ldcs, read-once) * L1-resident W reads,
//   rotating register accumulators with compile-time slots, ONE shuffle
//   butterfly, 19 direct STGs.
// Residue math: flat idx = o*2432 + t2*128 + 4*lane + j; 2432 % 19 == 0,
// 128 % 19 == 14  ->  r = (14*t2 + 4*lane + j) % 19, slot k = (14*t2+j) % 19.
// ---------------------------------------------------------------------------
__global__ __launch_bounds__(256, 4)
void score_kernel(const float* __restrict__ conv, float* __restrict__ out,
                  int k6, int nb) {
    const int lane = threadIdx.x & 31;
    const int wid  = threadIdx.x >> 5;
    const int bid  = blockIdx.x;

    // Bresenham: n6(bid) = floor(bid*k6/nb) six-blocks before this one.
    const int n6_lo = (int)(((long long)bid * k6) / nb);
    const int n6_hi = (int)(((long long)(bid + 1) * k6) / nb);
    const int cnt   = 7 - (n6_hi - n6_lo);        // 6 or 7 batches this block
    const int base  = bid * 7 - n6_lo;            // first batch of this block

    if (wid >= cnt) return;
    const int b = base + wid;

    const float4* c4 = reinterpret_cast<const float4*>(conv + (size_t)b * FLAT);
    const float4* w4 = reinterpret_cast<const float4*>(g_W);

    float acc[RC];
#pragma unroll
    for (int k = 0; k < RC; k++) acc[k] = 0.f;

    // 152 warp-iterations = 8 outer x 19 inner (slot pattern period 19)
    for (int o = 0; o < 8; o++) {
        const int ofs = o * (19 * 32) + lane;
#pragma unroll
        for (int t2 = 0; t2 < 19; t2++) {
            float4 cv = __ldcs(&c4[ofs + t2 * 32]);   // DRAM stream, read-once
            float4 wv = __ldg(&w4[ofs + t2 * 32]);    // L1-resident
            acc[(14 * t2 + 0) % RC] += cv.x * wv.x;
            acc[(14 * t2 + 1) % RC] += cv.y * wv.y;
            acc[(14 * t2 + 2) % RC] += cv.z * wv.z;
            acc[(14 * t2 + 3) % RC] += cv.w * wv.w;
        }
    }

    // Butterfly: lane l slot k holds r=(4l+k)%19; peer l+d has it at (k-4d)%19.
#pragma unroll
    for (int d = 16; d >= 1; d >>= 1) {
        float tmp[RC];
#pragma unroll
        for (int k = 0; k < RC; k++) {
            const int s = (k + 4 * RC - 4 * d) % RC;
            tmp[k] = __shfl_down_sync(0xffffffffu, acc[s], d);
        }
#pragma unroll
        for (int k = 0; k < RC; k++) acc[k] += tmp[k];
    }

    // Lane 0: slot k == relation k (r0 = 0). Direct stores, no atomics.
    if (lane == 0) {
        float* ob = out + (size_t)b * RC;
#pragma unroll
        for (int k = 0; k < RC; k++) ob[k] = acc[k];
    }
}

// ---------------------------------------------------------------------------
// Launch
// ---------------------------------------------------------------------------
extern "C" void kernel_launch(void* const* d_in, const int* in_sizes, int n_in,
                              void* d_out, int out_size) {
    const float* conv = nullptr;
    const float* R    = nullptr;
    const float* U    = nullptr;
    for (int i = 0; i < n_in; i++) {
        long long n = in_sizes[i];
        if (n == (long long)BATCH * FN * RC)      conv = (const float*)d_in[i];
        else if (n == (long long)RC * RD)         R    = (const float*)d_in[i];
        else if (n == (long long)FN * RD)         U    = (const float*)d_in[i];
    }
    float* out = (float*)d_out;

    // 4 blocks per SM, all resident in one wave. nsm clamped so that the
    // 6/7-batch decomposition is valid (6*NB <= 4096 <= 7*NB).
    int nsm = 148;
    cudaDeviceProp prop;
    if (cudaGetDeviceProperties(&prop, 0) == cudaSuccess)
        nsm = prop.multiProcessorCount;
    if (nsm < 147) nsm = 147;
    if (nsm > 170) nsm = 170;
    const int nb = 4 * nsm;            // 592 on B300, 608 on GB300
    const int k6 = 7 * nb - BATCH;     // number of 6-batch blocks

    cudaFuncSetAttribute(compute_w_kernel,
                         cudaFuncAttributeMaxDynamicSharedMemorySize, W_SMEM_BYTES);
    compute_w_kernel<<<128, 256, W_SMEM_BYTES>>>(U, R);
    score_kernel<<<nb, 256>>>(conv, out, k6, nb);
}